// round 5
// baseline (speedup 1.0000x reference)
#include <cuda_runtime.h>
#include <cuda_bf16.h>

#define S_GRID 14
#define INV_S (1.0f / 14.0f)
#define L_COORD 5.0f
#define L_NOOBJ 0.5f
#define CPB 256           // cells per block (= threads per block)
#define ROW_PAD 31        // smem row stride in floats (30 data + 1 pad, odd => conflict-free)

// Accumulators: [0]=reg, [1]=contain, [2]=noobj, [3]=cls
__device__ float g_acc[4];
__device__ unsigned int g_block_count;

__device__ __forceinline__ float iou_vs_tgt(float x, float y, float w, float h,
                                            float tx1, float ty1, float tx2, float ty2,
                                            float ta) {
    float cx = x * INV_S;
    float cy = y * INV_S;
    float x1 = cx - 0.5f * w, y1 = cy - 0.5f * h;
    float x2 = cx + 0.5f * w, y2 = cy + 0.5f * h;
    float lx = fmaxf(x1, tx1), ly = fmaxf(y1, ty1);
    float rx = fminf(x2, tx2), ry = fminf(y2, ty2);
    float iw = fmaxf(rx - lx, 0.0f), ih = fmaxf(ry - ly, 0.0f);
    float inter = iw * ih;
    float a1 = (x2 - x1) * (y2 - y1);
    return inter / (a1 + ta - inter);
}

__global__ void __launch_bounds__(CPB) yolo_fused_kernel(
    const float* __restrict__ pred,            // [ncells, 30]
    const float* __restrict__ tbox,            // [ncells, 4]
    const float* __restrict__ tcls,            // [ncells, 20]
    const unsigned int* __restrict__ objmap,   // [ncells] bool widened to 4B
    float* __restrict__ out,
    int ncells, float inv_n) {

    __shared__ float s_pred[CPB * ROW_PAD];    // 31 KB
    __shared__ float s_red[8][4];
    __shared__ bool s_is_last;

    int tid = threadIdx.x;
    int cell_base = blockIdx.x * CPB;
    int cells_here = min(CPB, ncells - cell_base);

    // ---- Stage: fully coalesced float4 stream of this block's pred rows ----
    // block's pred slice starts at float index cell_base*30, byte offset
    // cell_base*120 which is 16B-aligned for cell_base multiple of 4 (always,
    // since CPB=256). Total floats = cells_here*30.
    {
        int nfloats = cells_here * 30;
        int nf4 = nfloats >> 2;                       // full float4s
        const float4* src4 = reinterpret_cast<const float4*>(pred + (size_t)cell_base * 30);
        for (int f4 = tid; f4 < nf4; f4 += CPB) {
            float4 v = src4[f4];
            int f = f4 * 4;
            int r0 = f / 30,       c0 = f - r0 * 30;
            // write 4 consecutive logical floats (may cross a row boundary)
            int idx = r0 * ROW_PAD + c0;
            s_pred[idx] = v.x;
            f++; if (f - r0 * 30 == 30) { r0++; idx = r0 * ROW_PAD; } else idx++;
            s_pred[idx] = v.y;
            f++; if (f - r0 * 30 == 30) { r0++; idx = r0 * ROW_PAD; } else idx++;
            s_pred[idx] = v.z;
            f++; if (f - r0 * 30 == 30) { r0++; idx = r0 * ROW_PAD; } else idx++;
            s_pred[idx] = v.w;
        }
        // tail floats (nfloats not multiple of 4 only in partial last block)
        for (int f = nf4 * 4 + tid; f < nfloats; f += CPB) {
            int r = f / 30, c = f - r * 30;
            s_pred[r * ROW_PAD + c] = pred[(size_t)cell_base * 30 + f];
        }
    }
    __syncthreads();

    float reg = 0.0f, contain = 0.0f, noobj = 0.0f, cls = 0.0f;

    if (tid < cells_here) {
        int i = cell_base + tid;
        const float* pv = s_pred + tid * ROW_PAD;
        bool has_obj = objmap[i] != 0u;       // coalesced 4B load

        if (!has_obj) {
            float c1 = pv[4], c2 = pv[9];
            noobj = L_NOOBJ * (c1 * c1 + c2 * c2);
        } else {
            float4 tb = *reinterpret_cast<const float4*>(tbox + (size_t)i * 4);

            const float* tc = tcls + (size_t)i * 20;
            float csum = 0.0f;
            #pragma unroll
            for (int j = 0; j < 5; j++) {
                float4 t = *reinterpret_cast<const float4*>(tc + 4 * j);
                float d0 = pv[10 + 4 * j + 0] - t.x;
                float d1 = pv[10 + 4 * j + 1] - t.y;
                float d2 = pv[10 + 4 * j + 2] - t.z;
                float d3 = pv[10 + 4 * j + 3] - t.w;
                csum += d0 * d0 + d1 * d1 + d2 * d2 + d3 * d3;
            }
            cls = csum;

            float tcx = tb.x * INV_S, tcy = tb.y * INV_S;
            float tx1 = tcx - 0.5f * tb.z, ty1 = tcy - 0.5f * tb.w;
            float tx2 = tcx + 0.5f * tb.z, ty2 = tcy + 0.5f * tb.w;
            float ta = (tx2 - tx1) * (ty2 - ty1);

            float iou1 = iou_vs_tgt(pv[0], pv[1], pv[2], pv[3], tx1, ty1, tx2, ty2, ta);
            float iou2 = iou_vs_tgt(pv[5], pv[6], pv[7], pv[8], tx1, ty1, tx2, ty2, ta);

            bool take1 = iou1 > iou2;
            float best_iou = take1 ? iou1 : iou2;
            float bx = take1 ? pv[0] : pv[5];
            float by = take1 ? pv[1] : pv[6];
            float bw = take1 ? pv[2] : pv[7];
            float bh = take1 ? pv[3] : pv[8];
            float bc = take1 ? pv[4] : pv[9];

            float dx = bx - tb.x, dy = by - tb.y;
            float xy_err = dx * dx + dy * dy;
            float dw = sqrtf(bw) - sqrtf(tb.z);
            float dh = sqrtf(bh) - sqrtf(tb.w);
            float wh_err = dw * dw + dh * dh;
            reg = L_COORD * (xy_err + wh_err);

            float dc = bc - best_iou;
            contain = dc * dc;
        }
    }

    // ---- Reduction ----
    #pragma unroll
    for (int off = 16; off > 0; off >>= 1) {
        reg     += __shfl_down_sync(0xFFFFFFFFu, reg, off);
        contain += __shfl_down_sync(0xFFFFFFFFu, contain, off);
        noobj   += __shfl_down_sync(0xFFFFFFFFu, noobj, off);
        cls     += __shfl_down_sync(0xFFFFFFFFu, cls, off);
    }

    int lane = tid & 31;
    int warp = tid >> 5;
    if (lane == 0) {
        s_red[warp][0] = reg;
        s_red[warp][1] = contain;
        s_red[warp][2] = noobj;
        s_red[warp][3] = cls;
    }
    __syncthreads();

    if (warp == 0) {
        int comp = lane >> 3;     // 0..3
        int w    = lane & 7;      // 0..7
        float v = s_red[w][comp];
        v += __shfl_down_sync(0xFFFFFFFFu, v, 4);
        v += __shfl_down_sync(0xFFFFFFFFu, v, 2);
        v += __shfl_down_sync(0xFFFFFFFFu, v, 1);
        if (w == 0) atomicAdd(&g_acc[comp], v);
        __syncwarp();
        if (lane == 0) {
            __threadfence();
            unsigned int done = atomicAdd(&g_block_count, 1u);
            s_is_last = (done == gridDim.x - 1);
        }
    }
    __syncthreads();

    if (s_is_last && tid == 0) {
        float r  = g_acc[0];
        float ct = g_acc[1];
        float no = g_acc[2];
        float cl = g_acc[3];
        float total = r + ct + no + cl;
        out[0] = total * inv_n;
        out[1] = r  * inv_n;
        out[2] = ct * inv_n;
        out[3] = no * inv_n;
        out[4] = cl * inv_n;
        g_acc[0] = 0.0f; g_acc[1] = 0.0f; g_acc[2] = 0.0f; g_acc[3] = 0.0f;
        g_block_count = 0u;
        __threadfence();
    }
}

extern "C" void kernel_launch(void* const* d_in, const int* in_sizes, int n_in,
                              void* d_out, int out_size) {
    const float* pred = (const float*)d_in[0];
    const float* tbox = (const float*)d_in[1];
    const float* tcls = (const float*)d_in[2];
    const unsigned int* objmap = (const unsigned int*)d_in[3];

    int ncells = in_sizes[1] / 4;             // target_boxes has 4 per cell
    int n_imgs = ncells / (S_GRID * S_GRID);  // 4096

    int blocks = (ncells + CPB - 1) / CPB;    // 3136
    yolo_fused_kernel<<<blocks, CPB>>>(pred, tbox, tcls, objmap,
                                       (float*)d_out, ncells,
                                       1.0f / (float)n_imgs);
}

// round 6
// speedup vs baseline: 1.1221x; 1.1221x over previous
#include <cuda_runtime.h>
#include <cuda_bf16.h>

#define S_GRID 14
#define INV_S (1.0f / 14.0f)
#define L_COORD 5.0f
#define L_NOOBJ 0.5f
#define CPB 256           // cells per block (= threads per block)

// Accumulators: [0]=reg, [1]=contain, [2]=noobj, [3]=cls
__device__ float g_acc[4];
__device__ unsigned int g_block_count;

__device__ __forceinline__ float iou_vs_tgt(float x, float y, float w, float h,
                                            float tx1, float ty1, float tx2, float ty2,
                                            float ta) {
    float cx = x * INV_S;
    float cy = y * INV_S;
    float x1 = cx - 0.5f * w, y1 = cy - 0.5f * h;
    float x2 = cx + 0.5f * w, y2 = cy + 0.5f * h;
    float lx = fmaxf(x1, tx1), ly = fmaxf(y1, ty1);
    float rx = fminf(x2, tx2), ry = fminf(y2, ty2);
    float iw = fmaxf(rx - lx, 0.0f), ih = fmaxf(ry - ly, 0.0f);
    float inter = iw * ih;
    float a1 = (x2 - x1) * (y2 - y1);
    return inter / (a1 + ta - inter);
}

__global__ void __launch_bounds__(CPB) yolo_fused_kernel(
    const float* __restrict__ pred,            // [ncells, 30]
    const float* __restrict__ tbox,            // [ncells, 4]
    const float* __restrict__ tcls,            // [ncells, 20]
    const unsigned int* __restrict__ objmap,   // [ncells] bool widened to 4B
    float* __restrict__ out,
    int ncells, float inv_n) {

    // Raw (row-major, unpadded) copy of this block's pred slice: 256*30 floats.
    __shared__ float s_pred[CPB * 30];         // 30 KB
    __shared__ float s_red[8][4];
    __shared__ bool s_is_last;

    int tid = threadIdx.x;
    int cell_base = blockIdx.x * CPB;
    int i = cell_base + tid;

    // Issue the objmap load first (independent of staging) so the obj-path
    // branch resolves as early as possible.
    bool in_range = (i < ncells);
    unsigned int flag = in_range ? objmap[i] : 0u;

    // ---- Stage: zero-arithmetic coalesced float4 stream ----
    // ncells = 3136*256 so every block is full: exactly 1920 float4s.
    {
        const float4* src4 = reinterpret_cast<const float4*>(pred + (size_t)cell_base * 30);
        float4* dst4 = reinterpret_cast<float4*>(s_pred);
        int cells_here = min(CPB, ncells - cell_base);
        int nf4 = (cells_here * 30) >> 2;
        #pragma unroll
        for (int k = 0; k < 8; k++) {
            int f4 = tid + k * CPB;
            if (f4 < nf4) dst4[f4] = src4[f4];
        }
    }
    __syncthreads();

    float reg = 0.0f, contain = 0.0f, noobj = 0.0f, cls = 0.0f;

    if (in_range) {
        const float* pv = s_pred + tid * 30;

        if (flag == 0u) {
            float c1 = pv[4], c2 = pv[9];
            noobj = L_NOOBJ * (c1 * c1 + c2 * c2);
        } else {
            float4 tb = *reinterpret_cast<const float4*>(tbox + (size_t)i * 4);

            const float* tc = tcls + (size_t)i * 20;
            float csum = 0.0f;
            #pragma unroll
            for (int j = 0; j < 5; j++) {
                float4 t = *reinterpret_cast<const float4*>(tc + 4 * j);
                float d0 = pv[10 + 4 * j + 0] - t.x;
                float d1 = pv[10 + 4 * j + 1] - t.y;
                float d2 = pv[10 + 4 * j + 2] - t.z;
                float d3 = pv[10 + 4 * j + 3] - t.w;
                csum += d0 * d0 + d1 * d1 + d2 * d2 + d3 * d3;
            }
            cls = csum;

            float tcx = tb.x * INV_S, tcy = tb.y * INV_S;
            float tx1 = tcx - 0.5f * tb.z, ty1 = tcy - 0.5f * tb.w;
            float tx2 = tcx + 0.5f * tb.z, ty2 = tcy + 0.5f * tb.w;
            float ta = (tx2 - tx1) * (ty2 - ty1);

            float iou1 = iou_vs_tgt(pv[0], pv[1], pv[2], pv[3], tx1, ty1, tx2, ty2, ta);
            float iou2 = iou_vs_tgt(pv[5], pv[6], pv[7], pv[8], tx1, ty1, tx2, ty2, ta);

            bool take1 = iou1 > iou2;
            float best_iou = take1 ? iou1 : iou2;
            float bx = take1 ? pv[0] : pv[5];
            float by = take1 ? pv[1] : pv[6];
            float bw = take1 ? pv[2] : pv[7];
            float bh = take1 ? pv[3] : pv[8];
            float bc = take1 ? pv[4] : pv[9];

            float dx = bx - tb.x, dy = by - tb.y;
            float xy_err = dx * dx + dy * dy;
            float dw = sqrtf(bw) - sqrtf(tb.z);
            float dh = sqrtf(bh) - sqrtf(tb.w);
            float wh_err = dw * dw + dh * dh;
            reg = L_COORD * (xy_err + wh_err);

            float dc = bc - best_iou;
            contain = dc * dc;
        }
    }

    // ---- Reduction ----
    #pragma unroll
    for (int off = 16; off > 0; off >>= 1) {
        reg     += __shfl_down_sync(0xFFFFFFFFu, reg, off);
        contain += __shfl_down_sync(0xFFFFFFFFu, contain, off);
        noobj   += __shfl_down_sync(0xFFFFFFFFu, noobj, off);
        cls     += __shfl_down_sync(0xFFFFFFFFu, cls, off);
    }

    int lane = tid & 31;
    int warp = tid >> 5;
    if (lane == 0) {
        s_red[warp][0] = reg;
        s_red[warp][1] = contain;
        s_red[warp][2] = noobj;
        s_red[warp][3] = cls;
    }
    __syncthreads();

    if (warp == 0) {
        int comp = lane >> 3;     // 0..3
        int w    = lane & 7;      // 0..7
        float v = s_red[w][comp];
        v += __shfl_down_sync(0xFFFFFFFFu, v, 4);
        v += __shfl_down_sync(0xFFFFFFFFu, v, 2);
        v += __shfl_down_sync(0xFFFFFFFFu, v, 1);
        if (w == 0) atomicAdd(&g_acc[comp], v);
        __syncwarp();
        if (lane == 0) {
            __threadfence();
            unsigned int done = atomicAdd(&g_block_count, 1u);
            s_is_last = (done == gridDim.x - 1);
        }
    }
    __syncthreads();

    if (s_is_last && tid == 0) {
        float r  = g_acc[0];
        float ct = g_acc[1];
        float no = g_acc[2];
        float cl = g_acc[3];
        float total = r + ct + no + cl;
        out[0] = total * inv_n;
        out[1] = r  * inv_n;
        out[2] = ct * inv_n;
        out[3] = no * inv_n;
        out[4] = cl * inv_n;
        g_acc[0] = 0.0f; g_acc[1] = 0.0f; g_acc[2] = 0.0f; g_acc[3] = 0.0f;
        g_block_count = 0u;
        __threadfence();
    }
}

extern "C" void kernel_launch(void* const* d_in, const int* in_sizes, int n_in,
                              void* d_out, int out_size) {
    const float* pred = (const float*)d_in[0];
    const float* tbox = (const float*)d_in[1];
    const float* tcls = (const float*)d_in[2];
    const unsigned int* objmap = (const unsigned int*)d_in[3];

    int ncells = in_sizes[1] / 4;             // target_boxes has 4 per cell
    int n_imgs = ncells / (S_GRID * S_GRID);  // 4096

    int blocks = (ncells + CPB - 1) / CPB;    // 3136
    yolo_fused_kernel<<<blocks, CPB>>>(pred, tbox, tcls, objmap,
                                       (float*)d_out, ncells,
                                       1.0f / (float)n_imgs);
}

// round 7
// speedup vs baseline: 1.1989x; 1.0685x over previous
#include <cuda_runtime.h>
#include <cuda_bf16.h>
#include <cuda_pipeline_primitives.h>

#define S_GRID 14
#define INV_S (1.0f / 14.0f)
#define L_COORD 5.0f
#define L_NOOBJ 0.5f
#define CPB 256                 // cells per tile (= threads per block)
#define NF4_FULL ((CPB * 30) / 4)   // 1920 float4 per full tile

// Accumulators: [0]=reg, [1]=contain, [2]=noobj, [3]=cls
__device__ float g_acc[4];
__device__ unsigned int g_block_count;

__device__ __forceinline__ float iou_vs_tgt(float x, float y, float w, float h,
                                            float tx1, float ty1, float tx2, float ty2,
                                            float ta) {
    float cx = x * INV_S;
    float cy = y * INV_S;
    float x1 = cx - 0.5f * w, y1 = cy - 0.5f * h;
    float x2 = cx + 0.5f * w, y2 = cy + 0.5f * h;
    float lx = fmaxf(x1, tx1), ly = fmaxf(y1, ty1);
    float rx = fminf(x2, tx2), ry = fminf(y2, ty2);
    float iw = fmaxf(rx - lx, 0.0f), ih = fmaxf(ry - ly, 0.0f);
    float inter = iw * ih;
    float a1 = (x2 - x1) * (y2 - y1);
    return inter / (a1 + ta - inter);
}

// Issue async copy of one tile's pred rows into a smem buffer.
__device__ __forceinline__ void stage_tile_async(
    float* __restrict__ sbuf, const float* __restrict__ pred,
    int tile, int ncells, int tid) {

    int cell_base = tile * CPB;
    int cells_here = min(CPB, ncells - cell_base);
    const float4* src4 = reinterpret_cast<const float4*>(pred + (size_t)cell_base * 30);
    float4* dst4 = reinterpret_cast<float4*>(sbuf);
    int nf4 = (cells_here * 30) >> 2;
    if (nf4 == NF4_FULL) {
        #pragma unroll
        for (int k = 0; k < 8; k++) {
            int f4 = tid + k * CPB;
            if (f4 < NF4_FULL)
                __pipeline_memcpy_async(&dst4[f4], &src4[f4], 16);
        }
    } else {
        for (int f4 = tid; f4 < nf4; f4 += CPB)
            __pipeline_memcpy_async(&dst4[f4], &src4[f4], 16);
        // scalar tail (only possible on a partial last tile)
        int nfloats = cells_here * 30;
        for (int f = nf4 * 4 + tid; f < nfloats; f += CPB)
            sbuf[f] = pred[(size_t)cell_base * 30 + f];
    }
}

__global__ void __launch_bounds__(CPB) yolo_persistent_kernel(
    const float* __restrict__ pred,            // [ncells, 30]
    const float* __restrict__ tbox,            // [ncells, 4]
    const float* __restrict__ tcls,            // [ncells, 20]
    const unsigned int* __restrict__ objmap,   // [ncells] bool widened to 4B
    float* __restrict__ out,
    int ncells, int ntiles, float inv_n) {

    __shared__ float s_pred[2][CPB * 30];      // 2 x 30 KB
    __shared__ float s_red[8][4];
    __shared__ bool s_is_last;

    int tid = threadIdx.x;

    float reg = 0.0f, contain = 0.0f, noobj = 0.0f, cls = 0.0f;

    int tile = blockIdx.x;
    int b = 0;

    if (tile < ntiles) {
        // Prologue: stage first tile
        stage_tile_async(s_pred[0], pred, tile, ncells, tid);
        __pipeline_commit();

        for (; tile < ntiles; tile += gridDim.x) {
            int i = tile * CPB + tid;
            bool in_range = (i < ncells);
            unsigned int flag = in_range ? objmap[i] : 0u;   // overlaps pipeline wait

            int next = tile + gridDim.x;
            if (next < ntiles) {
                stage_tile_async(s_pred[b ^ 1], pred, next, ncells, tid);
                __pipeline_commit();
                __pipeline_wait_prior(1);   // current tile's group done
            } else {
                __pipeline_wait_prior(0);
            }
            __syncthreads();                 // staged data visible block-wide

            if (in_range) {
                const float* pv = s_pred[b] + tid * 30;

                if (flag == 0u) {
                    float c1 = pv[4], c2 = pv[9];
                    noobj += L_NOOBJ * (c1 * c1 + c2 * c2);
                } else {
                    float4 tb = *reinterpret_cast<const float4*>(tbox + (size_t)i * 4);

                    const float* tc = tcls + (size_t)i * 20;
                    float csum = 0.0f;
                    #pragma unroll
                    for (int j = 0; j < 5; j++) {
                        float4 t = *reinterpret_cast<const float4*>(tc + 4 * j);
                        float d0 = pv[10 + 4 * j + 0] - t.x;
                        float d1 = pv[10 + 4 * j + 1] - t.y;
                        float d2 = pv[10 + 4 * j + 2] - t.z;
                        float d3 = pv[10 + 4 * j + 3] - t.w;
                        csum += d0 * d0 + d1 * d1 + d2 * d2 + d3 * d3;
                    }
                    cls += csum;

                    float tcx = tb.x * INV_S, tcy = tb.y * INV_S;
                    float tx1 = tcx - 0.5f * tb.z, ty1 = tcy - 0.5f * tb.w;
                    float tx2 = tcx + 0.5f * tb.z, ty2 = tcy + 0.5f * tb.w;
                    float ta = (tx2 - tx1) * (ty2 - ty1);

                    float iou1 = iou_vs_tgt(pv[0], pv[1], pv[2], pv[3], tx1, ty1, tx2, ty2, ta);
                    float iou2 = iou_vs_tgt(pv[5], pv[6], pv[7], pv[8], tx1, ty1, tx2, ty2, ta);

                    bool take1 = iou1 > iou2;
                    float best_iou = take1 ? iou1 : iou2;
                    float bx = take1 ? pv[0] : pv[5];
                    float by = take1 ? pv[1] : pv[6];
                    float bw = take1 ? pv[2] : pv[7];
                    float bh = take1 ? pv[3] : pv[8];
                    float bc = take1 ? pv[4] : pv[9];

                    float dx = bx - tb.x, dy = by - tb.y;
                    float xy_err = dx * dx + dy * dy;
                    float dw = sqrtf(bw) - sqrtf(tb.z);
                    float dh = sqrtf(bh) - sqrtf(tb.w);
                    float wh_err = dw * dw + dh * dh;
                    reg += L_COORD * (xy_err + wh_err);

                    float dc = bc - best_iou;
                    contain += dc * dc;
                }
            }
            __syncthreads();                 // compute done before buffer reuse
            b ^= 1;
        }
    }

    // ---- One reduction per block ----
    #pragma unroll
    for (int off = 16; off > 0; off >>= 1) {
        reg     += __shfl_down_sync(0xFFFFFFFFu, reg, off);
        contain += __shfl_down_sync(0xFFFFFFFFu, contain, off);
        noobj   += __shfl_down_sync(0xFFFFFFFFu, noobj, off);
        cls     += __shfl_down_sync(0xFFFFFFFFu, cls, off);
    }

    int lane = tid & 31;
    int warp = tid >> 5;
    if (lane == 0) {
        s_red[warp][0] = reg;
        s_red[warp][1] = contain;
        s_red[warp][2] = noobj;
        s_red[warp][3] = cls;
    }
    __syncthreads();

    if (warp == 0) {
        int comp = lane >> 3;     // 0..3
        int w    = lane & 7;      // 0..7
        float v = s_red[w][comp];
        v += __shfl_down_sync(0xFFFFFFFFu, v, 4);
        v += __shfl_down_sync(0xFFFFFFFFu, v, 2);
        v += __shfl_down_sync(0xFFFFFFFFu, v, 1);
        if (w == 0) atomicAdd(&g_acc[comp], v);
        __syncwarp();
        if (lane == 0) {
            __threadfence();
            unsigned int done = atomicAdd(&g_block_count, 1u);
            s_is_last = (done == gridDim.x - 1);
        }
    }
    __syncthreads();

    if (s_is_last && tid == 0) {
        float r  = g_acc[0];
        float ct = g_acc[1];
        float no = g_acc[2];
        float cl = g_acc[3];
        float total = r + ct + no + cl;
        out[0] = total * inv_n;
        out[1] = r  * inv_n;
        out[2] = ct * inv_n;
        out[3] = no * inv_n;
        out[4] = cl * inv_n;
        g_acc[0] = 0.0f; g_acc[1] = 0.0f; g_acc[2] = 0.0f; g_acc[3] = 0.0f;
        g_block_count = 0u;
        __threadfence();
    }
}

extern "C" void kernel_launch(void* const* d_in, const int* in_sizes, int n_in,
                              void* d_out, int out_size) {
    const float* pred = (const float*)d_in[0];
    const float* tbox = (const float*)d_in[1];
    const float* tcls = (const float*)d_in[2];
    const unsigned int* objmap = (const unsigned int*)d_in[3];

    int ncells = in_sizes[1] / 4;             // target_boxes has 4 per cell
    int n_imgs = ncells / (S_GRID * S_GRID);  // 4096
    int ntiles = (ncells + CPB - 1) / CPB;    // 3136

    int dev = 0, sms = 148;
    cudaGetDevice(&dev);
    cudaDeviceGetAttribute(&sms, cudaDevAttrMultiProcessorCount, dev);
    int blocks = sms * 3;                     // 3 co-resident blocks/SM (60KB smem each)
    if (blocks > ntiles) blocks = ntiles;

    yolo_persistent_kernel<<<blocks, CPB>>>(pred, tbox, tcls, objmap,
                                            (float*)d_out, ncells, ntiles,
                                            1.0f / (float)n_imgs);
}

// round 8
// speedup vs baseline: 1.2002x; 1.0011x over previous
#include <cuda_runtime.h>
#include <cuda_bf16.h>
#include <cuda_pipeline_primitives.h>

#define S_GRID 14
#define INV_S (1.0f / 14.0f)
#define L_COORD 5.0f
#define L_NOOBJ 0.5f
#define CPB 256                 // cells per tile (= threads per block)
#define NF4_FULL ((CPB * 30) / 4)   // 1920 float4 per full tile

// Accumulators: [0]=reg, [1]=contain, [2]=noobj, [3]=cls
__device__ float g_acc[4];
__device__ unsigned int g_block_count;

__device__ __forceinline__ float iou_vs_tgt(float x, float y, float w, float h,
                                            float tx1, float ty1, float tx2, float ty2,
                                            float ta) {
    float cx = x * INV_S;
    float cy = y * INV_S;
    float x1 = cx - 0.5f * w, y1 = cy - 0.5f * h;
    float x2 = cx + 0.5f * w, y2 = cy + 0.5f * h;
    float lx = fmaxf(x1, tx1), ly = fmaxf(y1, ty1);
    float rx = fminf(x2, tx2), ry = fminf(y2, ty2);
    float iw = fmaxf(rx - lx, 0.0f), ih = fmaxf(ry - ly, 0.0f);
    float inter = iw * ih;
    float a1 = (x2 - x1) * (y2 - y1);
    return inter / (a1 + ta - inter);
}

// Issue async copy of one tile's pred rows into a smem buffer.
__device__ __forceinline__ void stage_tile_async(
    float* __restrict__ sbuf, const float* __restrict__ pred,
    int tile, int ncells, int tid) {

    int cell_base = tile * CPB;
    int cells_here = min(CPB, ncells - cell_base);
    const float4* src4 = reinterpret_cast<const float4*>(pred + (size_t)cell_base * 30);
    float4* dst4 = reinterpret_cast<float4*>(sbuf);
    int nf4 = (cells_here * 30) >> 2;
    if (nf4 == NF4_FULL) {
        #pragma unroll
        for (int k = 0; k < 8; k++) {
            int f4 = tid + k * CPB;
            if (f4 < NF4_FULL)
                __pipeline_memcpy_async(&dst4[f4], &src4[f4], 16);
        }
    } else {
        for (int f4 = tid; f4 < nf4; f4 += CPB)
            __pipeline_memcpy_async(&dst4[f4], &src4[f4], 16);
        // scalar tail (only possible on a partial last tile)
        int nfloats = cells_here * 30;
        for (int f = nf4 * 4 + tid; f < nfloats; f += CPB)
            sbuf[f] = pred[(size_t)cell_base * 30 + f];
    }
}

__global__ void __launch_bounds__(CPB) yolo_persistent_kernel(
    const float* __restrict__ pred,            // [ncells, 30]
    const float* __restrict__ tbox,            // [ncells, 4]
    const float* __restrict__ tcls,            // [ncells, 20]
    const unsigned int* __restrict__ objmap,   // [ncells] bool widened to 4B
    float* __restrict__ out,
    int ncells, int ntiles, float inv_n) {

    __shared__ float s_pred[2][CPB * 30];      // 2 x 30 KB
    __shared__ float s_red[8][4];
    __shared__ bool s_is_last;

    int tid = threadIdx.x;

    float reg = 0.0f, contain = 0.0f, noobj = 0.0f, cls = 0.0f;

    int tile = blockIdx.x;
    int b = 0;

    if (tile < ntiles) {
        // Prologue: stage first tile
        stage_tile_async(s_pred[0], pred, tile, ncells, tid);
        __pipeline_commit();

        for (; tile < ntiles; tile += gridDim.x) {
            int i = tile * CPB + tid;
            bool in_range = (i < ncells);
            unsigned int flag = in_range ? objmap[i] : 0u;   // overlaps pipeline wait

            int next = tile + gridDim.x;
            if (next < ntiles) {
                stage_tile_async(s_pred[b ^ 1], pred, next, ncells, tid);
                __pipeline_commit();
                __pipeline_wait_prior(1);   // current tile's group done
            } else {
                __pipeline_wait_prior(0);
            }
            __syncthreads();                 // staged data visible block-wide

            if (in_range) {
                const float* pv = s_pred[b] + tid * 30;

                if (flag == 0u) {
                    float c1 = pv[4], c2 = pv[9];
                    noobj += L_NOOBJ * (c1 * c1 + c2 * c2);
                } else {
                    float4 tb = *reinterpret_cast<const float4*>(tbox + (size_t)i * 4);

                    const float* tc = tcls + (size_t)i * 20;
                    float csum = 0.0f;
                    #pragma unroll
                    for (int j = 0; j < 5; j++) {
                        float4 t = *reinterpret_cast<const float4*>(tc + 4 * j);
                        float d0 = pv[10 + 4 * j + 0] - t.x;
                        float d1 = pv[10 + 4 * j + 1] - t.y;
                        float d2 = pv[10 + 4 * j + 2] - t.z;
                        float d3 = pv[10 + 4 * j + 3] - t.w;
                        csum += d0 * d0 + d1 * d1 + d2 * d2 + d3 * d3;
                    }
                    cls += csum;

                    float tcx = tb.x * INV_S, tcy = tb.y * INV_S;
                    float tx1 = tcx - 0.5f * tb.z, ty1 = tcy - 0.5f * tb.w;
                    float tx2 = tcx + 0.5f * tb.z, ty2 = tcy + 0.5f * tb.w;
                    float ta = (tx2 - tx1) * (ty2 - ty1);

                    float iou1 = iou_vs_tgt(pv[0], pv[1], pv[2], pv[3], tx1, ty1, tx2, ty2, ta);
                    float iou2 = iou_vs_tgt(pv[5], pv[6], pv[7], pv[8], tx1, ty1, tx2, ty2, ta);

                    bool take1 = iou1 > iou2;
                    float best_iou = take1 ? iou1 : iou2;
                    float bx = take1 ? pv[0] : pv[5];
                    float by = take1 ? pv[1] : pv[6];
                    float bw = take1 ? pv[2] : pv[7];
                    float bh = take1 ? pv[3] : pv[8];
                    float bc = take1 ? pv[4] : pv[9];

                    float dx = bx - tb.x, dy = by - tb.y;
                    float xy_err = dx * dx + dy * dy;
                    float dw = sqrtf(bw) - sqrtf(tb.z);
                    float dh = sqrtf(bh) - sqrtf(tb.w);
                    float wh_err = dw * dw + dh * dh;
                    reg += L_COORD * (xy_err + wh_err);

                    float dc = bc - best_iou;
                    contain += dc * dc;
                }
            }
            __syncthreads();                 // compute done before buffer reuse
            b ^= 1;
        }
    }

    // ---- One reduction per block ----
    #pragma unroll
    for (int off = 16; off > 0; off >>= 1) {
        reg     += __shfl_down_sync(0xFFFFFFFFu, reg, off);
        contain += __shfl_down_sync(0xFFFFFFFFu, contain, off);
        noobj   += __shfl_down_sync(0xFFFFFFFFu, noobj, off);
        cls     += __shfl_down_sync(0xFFFFFFFFu, cls, off);
    }

    int lane = tid & 31;
    int warp = tid >> 5;
    if (lane == 0) {
        s_red[warp][0] = reg;
        s_red[warp][1] = contain;
        s_red[warp][2] = noobj;
        s_red[warp][3] = cls;
    }
    __syncthreads();

    if (warp == 0) {
        int comp = lane >> 3;     // 0..3
        int w    = lane & 7;      // 0..7
        float v = s_red[w][comp];
        v += __shfl_down_sync(0xFFFFFFFFu, v, 4);
        v += __shfl_down_sync(0xFFFFFFFFu, v, 2);
        v += __shfl_down_sync(0xFFFFFFFFu, v, 1);
        if (w == 0) atomicAdd(&g_acc[comp], v);
        __syncwarp();
        if (lane == 0) {
            __threadfence();
            unsigned int done = atomicAdd(&g_block_count, 1u);
            s_is_last = (done == gridDim.x - 1);
        }
    }
    __syncthreads();

    if (s_is_last && tid == 0) {
        float r  = g_acc[0];
        float ct = g_acc[1];
        float no = g_acc[2];
        float cl = g_acc[3];
        float total = r + ct + no + cl;
        out[0] = total * inv_n;
        out[1] = r  * inv_n;
        out[2] = ct * inv_n;
        out[3] = no * inv_n;
        out[4] = cl * inv_n;
        g_acc[0] = 0.0f; g_acc[1] = 0.0f; g_acc[2] = 0.0f; g_acc[3] = 0.0f;
        g_block_count = 0u;
        __threadfence();
    }
}

extern "C" void kernel_launch(void* const* d_in, const int* in_sizes, int n_in,
                              void* d_out, int out_size) {
    const float* pred = (const float*)d_in[0];
    const float* tbox = (const float*)d_in[1];
    const float* tcls = (const float*)d_in[2];
    const unsigned int* objmap = (const unsigned int*)d_in[3];

    int ncells = in_sizes[1] / 4;             // target_boxes has 4 per cell
    int n_imgs = ncells / (S_GRID * S_GRID);  // 4096
    int ntiles = (ncells + CPB - 1) / CPB;    // 3136

    int dev = 0, sms = 148;
    cudaGetDevice(&dev);
    cudaDeviceGetAttribute(&sms, cudaDevAttrMultiProcessorCount, dev);
    int blocks = sms * 3;                     // 3 co-resident blocks/SM (60KB smem each)
    if (blocks > ntiles) blocks = ntiles;

    yolo_persistent_kernel<<<blocks, CPB>>>(pred, tbox, tcls, objmap,
                                            (float*)d_out, ncells, ntiles,
                                            1.0f / (float)n_imgs);
}

// round 9
// speedup vs baseline: 1.2121x; 1.0099x over previous
#include <cuda_runtime.h>
#include <cuda_bf16.h>
#include <cuda_pipeline_primitives.h>

#define S_GRID 14
#define INV_S (1.0f / 14.0f)
#define L_COORD 5.0f
#define L_NOOBJ 0.5f
#define CPB 128                      // cells per tile = threads per block
#define NF4_FULL ((CPB * 30) / 4)    // 960 float4 per full tile

// Accumulators: [0]=reg, [1]=contain, [2]=noobj, [3]=cls
__device__ float g_acc[4];
__device__ unsigned int g_block_count;

__device__ __forceinline__ float iou_vs_tgt(float x, float y, float w, float h,
                                            float tx1, float ty1, float tx2, float ty2,
                                            float ta) {
    float cx = x * INV_S;
    float cy = y * INV_S;
    float x1 = cx - 0.5f * w, y1 = cy - 0.5f * h;
    float x2 = cx + 0.5f * w, y2 = cy + 0.5f * h;
    float lx = fmaxf(x1, tx1), ly = fmaxf(y1, ty1);
    float rx = fminf(x2, tx2), ry = fminf(y2, ty2);
    float iw = fmaxf(rx - lx, 0.0f), ih = fmaxf(ry - ly, 0.0f);
    float inter = iw * ih;
    float a1 = (x2 - x1) * (y2 - y1);
    return inter / (a1 + ta - inter);
}

__device__ __forceinline__ void stage_tile_async(
    float* __restrict__ sbuf, const float* __restrict__ pred,
    int tile, int ncells, int tid) {

    int cell_base = tile * CPB;
    int cells_here = min(CPB, ncells - cell_base);
    const float4* src4 = reinterpret_cast<const float4*>(pred + (size_t)cell_base * 30);
    float4* dst4 = reinterpret_cast<float4*>(sbuf);
    int nf4 = (cells_here * 30) >> 2;
    if (nf4 == NF4_FULL) {
        #pragma unroll
        for (int k = 0; k < 8; k++) {
            int f4 = tid + k * CPB;
            if (f4 < NF4_FULL)
                __pipeline_memcpy_async(&dst4[f4], &src4[f4], 16);
        }
    } else {
        for (int f4 = tid; f4 < nf4; f4 += CPB)
            __pipeline_memcpy_async(&dst4[f4], &src4[f4], 16);
        int nfloats = cells_here * 30;
        for (int f = nf4 * 4 + tid; f < nfloats; f += CPB)
            sbuf[f] = pred[(size_t)cell_base * 30 + f];
    }
}

__global__ void __launch_bounds__(CPB, 5) yolo_persistent_kernel(
    const float* __restrict__ pred,            // [ncells, 30]
    const float* __restrict__ tbox,            // [ncells, 4]
    const float* __restrict__ tcls,            // [ncells, 20]
    const unsigned int* __restrict__ objmap,   // [ncells] bool widened to 4B
    float* __restrict__ out,
    int ncells, int ntiles, float inv_n) {

    __shared__ float s_pred[2][CPB * 30];      // 2 x 15 KB
    __shared__ float s_red[4][4];
    __shared__ bool s_is_last;

    int tid = threadIdx.x;

    float reg = 0.0f, contain = 0.0f, noobj = 0.0f, cls = 0.0f;

    int tile = blockIdx.x;
    int b = 0;

    if (tile < ntiles) {
        stage_tile_async(s_pred[0], pred, tile, ncells, tid);
        __pipeline_commit();

        for (; tile < ntiles; tile += gridDim.x) {
            int i = tile * CPB + tid;
            bool in_range = (i < ncells);
            unsigned int flag = in_range ? objmap[i] : 0u;
            bool has_obj = (flag != 0u);

            // ---- Hoisted obj-path gathers: issued BEFORE the pipeline wait so
            // their DRAM latency overlaps the cp.async drain of this tile. ----
            float4 tb = make_float4(0.f, 0.f, 0.f, 0.f);
            float4 tcv[5];
            if (has_obj) {
                tb = __ldg(reinterpret_cast<const float4*>(tbox + (size_t)i * 4));
                const float4* tc4 = reinterpret_cast<const float4*>(tcls + (size_t)i * 20);
                #pragma unroll
                for (int j = 0; j < 5; j++) tcv[j] = __ldg(tc4 + j);
            }

            int next = tile + gridDim.x;
            if (next < ntiles) {
                stage_tile_async(s_pred[b ^ 1], pred, next, ncells, tid);
                __pipeline_commit();
                __pipeline_wait_prior(1);
            } else {
                __pipeline_wait_prior(0);
            }
            __syncthreads();

            if (in_range) {
                const float* pv = s_pred[b] + tid * 30;

                if (!has_obj) {
                    float c1 = pv[4], c2 = pv[9];
                    noobj += L_NOOBJ * (c1 * c1 + c2 * c2);
                } else {
                    float csum = 0.0f;
                    #pragma unroll
                    for (int j = 0; j < 5; j++) {
                        float d0 = pv[10 + 4 * j + 0] - tcv[j].x;
                        float d1 = pv[10 + 4 * j + 1] - tcv[j].y;
                        float d2 = pv[10 + 4 * j + 2] - tcv[j].z;
                        float d3 = pv[10 + 4 * j + 3] - tcv[j].w;
                        csum += d0 * d0 + d1 * d1 + d2 * d2 + d3 * d3;
                    }
                    cls += csum;

                    float tcx = tb.x * INV_S, tcy = tb.y * INV_S;
                    float tx1 = tcx - 0.5f * tb.z, ty1 = tcy - 0.5f * tb.w;
                    float tx2 = tcx + 0.5f * tb.z, ty2 = tcy + 0.5f * tb.w;
                    float ta = (tx2 - tx1) * (ty2 - ty1);

                    float iou1 = iou_vs_tgt(pv[0], pv[1], pv[2], pv[3], tx1, ty1, tx2, ty2, ta);
                    float iou2 = iou_vs_tgt(pv[5], pv[6], pv[7], pv[8], tx1, ty1, tx2, ty2, ta);

                    bool take1 = iou1 > iou2;
                    float best_iou = take1 ? iou1 : iou2;
                    float bx = take1 ? pv[0] : pv[5];
                    float by = take1 ? pv[1] : pv[6];
                    float bw = take1 ? pv[2] : pv[7];
                    float bh = take1 ? pv[3] : pv[8];
                    float bc = take1 ? pv[4] : pv[9];

                    float dx = bx - tb.x, dy = by - tb.y;
                    float xy_err = dx * dx + dy * dy;
                    float dw = sqrtf(bw) - sqrtf(tb.z);
                    float dh = sqrtf(bh) - sqrtf(tb.w);
                    float wh_err = dw * dw + dh * dh;
                    reg += L_COORD * (xy_err + wh_err);

                    float dc = bc - best_iou;
                    contain += dc * dc;
                }
            }
            __syncthreads();
            b ^= 1;
        }
    }

    // ---- One reduction per block (4 warps) ----
    #pragma unroll
    for (int off = 16; off > 0; off >>= 1) {
        reg     += __shfl_down_sync(0xFFFFFFFFu, reg, off);
        contain += __shfl_down_sync(0xFFFFFFFFu, contain, off);
        noobj   += __shfl_down_sync(0xFFFFFFFFu, noobj, off);
        cls     += __shfl_down_sync(0xFFFFFFFFu, cls, off);
    }

    int lane = tid & 31;
    int warp = tid >> 5;
    if (lane == 0) {
        s_red[warp][0] = reg;
        s_red[warp][1] = contain;
        s_red[warp][2] = noobj;
        s_red[warp][3] = cls;
    }
    __syncthreads();

    if (warp == 0) {
        // 4 components x 4 warps = 16 active lanes
        int comp = lane >> 2;     // 0..3 (lanes 0..15)
        int w    = lane & 3;      // 0..3
        float v = (lane < 16) ? s_red[w][comp] : 0.0f;
        v += __shfl_down_sync(0xFFFFFFFFu, v, 2);
        v += __shfl_down_sync(0xFFFFFFFFu, v, 1);
        if (lane < 16 && w == 0) atomicAdd(&g_acc[comp], v);
        __syncwarp();
        if (lane == 0) {
            __threadfence();
            unsigned int done = atomicAdd(&g_block_count, 1u);
            s_is_last = (done == gridDim.x - 1);
        }
    }
    __syncthreads();

    if (s_is_last && tid == 0) {
        float r  = g_acc[0];
        float ct = g_acc[1];
        float no = g_acc[2];
        float cl = g_acc[3];
        float total = r + ct + no + cl;
        out[0] = total * inv_n;
        out[1] = r  * inv_n;
        out[2] = ct * inv_n;
        out[3] = no * inv_n;
        out[4] = cl * inv_n;
        g_acc[0] = 0.0f; g_acc[1] = 0.0f; g_acc[2] = 0.0f; g_acc[3] = 0.0f;
        g_block_count = 0u;
        __threadfence();
    }
}

extern "C" void kernel_launch(void* const* d_in, const int* in_sizes, int n_in,
                              void* d_out, int out_size) {
    const float* pred = (const float*)d_in[0];
    const float* tbox = (const float*)d_in[1];
    const float* tcls = (const float*)d_in[2];
    const unsigned int* objmap = (const unsigned int*)d_in[3];

    int ncells = in_sizes[1] / 4;             // target_boxes has 4 per cell
    int n_imgs = ncells / (S_GRID * S_GRID);  // 4096
    int ntiles = (ncells + CPB - 1) / CPB;    // 6272

    int dev = 0, sms = 148;
    cudaGetDevice(&dev);
    cudaDeviceGetAttribute(&sms, cudaDevAttrMultiProcessorCount, dev);
    int blocks = sms * 5;                     // 5 co-resident blocks/SM
    if (blocks > ntiles) blocks = ntiles;

    yolo_persistent_kernel<<<blocks, CPB>>>(pred, tbox, tcls, objmap,
                                            (float*)d_out, ncells, ntiles,
                                            1.0f / (float)n_imgs);
}

// round 10
// speedup vs baseline: 1.2826x; 1.0581x over previous
#include <cuda_runtime.h>
#include <cuda_bf16.h>
#include <cuda_pipeline_primitives.h>

#define S_GRID 14
#define INV_S (1.0f / 14.0f)
#define L_COORD 5.0f
#define L_NOOBJ 0.5f
#define TPB 128                  // threads per block
#define WARPS 4                  // warps per block
#define WTILE 32                 // cells per warp-tile
#define TILE_F (WTILE * 30)      // 960 floats per tile
#define TILE_F4 (TILE_F / 4)     // 240 float4 per tile

// Accumulators: [0]=reg, [1]=contain, [2]=noobj, [3]=cls
__device__ float g_acc[4];
__device__ unsigned int g_block_count;

__device__ __forceinline__ float iou_vs_tgt(float x, float y, float w, float h,
                                            float tx1, float ty1, float tx2, float ty2,
                                            float ta) {
    float cx = x * INV_S;
    float cy = y * INV_S;
    float x1 = cx - 0.5f * w, y1 = cy - 0.5f * h;
    float x2 = cx + 0.5f * w, y2 = cy + 0.5f * h;
    float lx = fmaxf(x1, tx1), ly = fmaxf(y1, ty1);
    float rx = fminf(x2, tx2), ry = fminf(y2, ty2);
    float iw = fmaxf(rx - lx, 0.0f), ih = fmaxf(ry - ly, 0.0f);
    float inter = iw * ih;
    float a1 = (x2 - x1) * (y2 - y1);
    return inter / (a1 + ta - inter);
}

// Stage one warp-tile (32 cells x 30 floats) via cp.async. Lane-strided.
__device__ __forceinline__ void stage_warp_tile(
    float* __restrict__ sbuf, const float* __restrict__ pred,
    int tile, int ncells, int lane) {

    int cell_base = tile * WTILE;
    const float4* src4 = reinterpret_cast<const float4*>(pred + (size_t)cell_base * 30);
    float4* dst4 = reinterpret_cast<float4*>(sbuf);
    int cells_here = min(WTILE, ncells - cell_base);
    if (cells_here == WTILE) {
        // 240 float4: 8 strides of 32 lanes, last stride half-active (240-224=16)
        #pragma unroll
        for (int k = 0; k < 8; k++) {
            int f4 = lane + k * 32;
            if (f4 < TILE_F4)
                __pipeline_memcpy_async(&dst4[f4], &src4[f4], 16);
        }
    } else {
        int nf4 = (cells_here * 30) >> 2;
        for (int f4 = lane; f4 < nf4; f4 += 32)
            __pipeline_memcpy_async(&dst4[f4], &src4[f4], 16);
        int nfloats = cells_here * 30;
        for (int f = nf4 * 4 + lane; f < nfloats; f += 32)
            sbuf[f] = pred[(size_t)cell_base * 30 + f];
    }
}

__global__ void __launch_bounds__(TPB, 6) yolo_persistent_kernel(
    const float* __restrict__ pred,            // [ncells, 30]
    const float* __restrict__ tbox,            // [ncells, 4]
    const float* __restrict__ tcls,            // [ncells, 20]
    const unsigned int* __restrict__ objmap,   // [ncells] bool widened to 4B
    float* __restrict__ out,
    int ncells, int ntiles, int nwarps_total, float inv_n) {

    // Warp-private double buffers: [buf][warp][960]
    __shared__ float s_pred[2][WARPS][TILE_F];   // 30.7 KB
    __shared__ float s_red[WARPS][4];
    __shared__ bool s_is_last;

    int tid  = threadIdx.x;
    int lane = tid & 31;
    int warp = tid >> 5;
    int gwarp = blockIdx.x * WARPS + warp;      // global warp id

    float reg = 0.0f, contain = 0.0f, noobj = 0.0f, cls = 0.0f;

    int tile = gwarp;
    int b = 0;

    if (tile < ntiles) {
        stage_warp_tile(s_pred[0][warp], pred, tile, ncells, lane);
        __pipeline_commit();

        for (; tile < ntiles; tile += nwarps_total) {
            int i = tile * WTILE + lane;
            bool in_range = (i < ncells);
            unsigned int flag = in_range ? objmap[i] : 0u;
            bool has_obj = (flag != 0u);

            // Hoisted obj-path gathers: overlap the cp.async drain.
            float4 tb = make_float4(0.f, 0.f, 0.f, 0.f);
            float4 tcv[5];
            if (has_obj) {
                tb = __ldg(reinterpret_cast<const float4*>(tbox + (size_t)i * 4));
                const float4* tc4 = reinterpret_cast<const float4*>(tcls + (size_t)i * 20);
                #pragma unroll
                for (int j = 0; j < 5; j++) tcv[j] = __ldg(tc4 + j);
            }

            int next = tile + nwarps_total;
            if (next < ntiles) {
                stage_warp_tile(s_pred[b ^ 1][warp], pred, next, ncells, lane);
                __pipeline_commit();
                __pipeline_wait_prior(1);
            } else {
                __pipeline_wait_prior(0);
            }
            __syncwarp();     // warp-scope visibility of this warp's staged tile

            if (in_range) {
                const float* pv = s_pred[b][warp] + lane * 30;

                if (!has_obj) {
                    float c1 = pv[4], c2 = pv[9];
                    noobj += L_NOOBJ * (c1 * c1 + c2 * c2);
                } else {
                    float csum = 0.0f;
                    #pragma unroll
                    for (int j = 0; j < 5; j++) {
                        float d0 = pv[10 + 4 * j + 0] - tcv[j].x;
                        float d1 = pv[10 + 4 * j + 1] - tcv[j].y;
                        float d2 = pv[10 + 4 * j + 2] - tcv[j].z;
                        float d3 = pv[10 + 4 * j + 3] - tcv[j].w;
                        csum += d0 * d0 + d1 * d1 + d2 * d2 + d3 * d3;
                    }
                    cls += csum;

                    float tcx = tb.x * INV_S, tcy = tb.y * INV_S;
                    float tx1 = tcx - 0.5f * tb.z, ty1 = tcy - 0.5f * tb.w;
                    float tx2 = tcx + 0.5f * tb.z, ty2 = tcy + 0.5f * tb.w;
                    float ta = (tx2 - tx1) * (ty2 - ty1);

                    float iou1 = iou_vs_tgt(pv[0], pv[1], pv[2], pv[3], tx1, ty1, tx2, ty2, ta);
                    float iou2 = iou_vs_tgt(pv[5], pv[6], pv[7], pv[8], tx1, ty1, tx2, ty2, ta);

                    bool take1 = iou1 > iou2;
                    float best_iou = take1 ? iou1 : iou2;
                    float bx = take1 ? pv[0] : pv[5];
                    float by = take1 ? pv[1] : pv[6];
                    float bw = take1 ? pv[2] : pv[7];
                    float bh = take1 ? pv[3] : pv[8];
                    float bc = take1 ? pv[4] : pv[9];

                    float dx = bx - tb.x, dy = by - tb.y;
                    float xy_err = dx * dx + dy * dy;
                    float dw = sqrtf(bw) - sqrtf(tb.z);
                    float dh = sqrtf(bh) - sqrtf(tb.w);
                    float wh_err = dw * dw + dh * dh;
                    reg += L_COORD * (xy_err + wh_err);

                    float dc = bc - best_iou;
                    contain += dc * dc;
                }
            }
            __syncwarp();     // this warp done with buffer b before reuse
            b ^= 1;
        }
    }

    // ---- One reduction per block ----
    #pragma unroll
    for (int off = 16; off > 0; off >>= 1) {
        reg     += __shfl_down_sync(0xFFFFFFFFu, reg, off);
        contain += __shfl_down_sync(0xFFFFFFFFu, contain, off);
        noobj   += __shfl_down_sync(0xFFFFFFFFu, noobj, off);
        cls     += __shfl_down_sync(0xFFFFFFFFu, cls, off);
    }

    if (lane == 0) {
        s_red[warp][0] = reg;
        s_red[warp][1] = contain;
        s_red[warp][2] = noobj;
        s_red[warp][3] = cls;
    }
    __syncthreads();

    if (warp == 0) {
        // 4 components x 4 warps = 16 active lanes
        int comp = lane >> 2;     // 0..3 (lanes 0..15)
        int w    = lane & 3;      // 0..3
        float v = (lane < 16) ? s_red[w][comp] : 0.0f;
        v += __shfl_down_sync(0xFFFFFFFFu, v, 2);
        v += __shfl_down_sync(0xFFFFFFFFu, v, 1);
        if (lane < 16 && w == 0) atomicAdd(&g_acc[comp], v);
        __syncwarp();
        if (lane == 0) {
            __threadfence();
            unsigned int done = atomicAdd(&g_block_count, 1u);
            s_is_last = (done == gridDim.x - 1);
        }
    }
    __syncthreads();

    if (s_is_last && tid == 0) {
        float r  = g_acc[0];
        float ct = g_acc[1];
        float no = g_acc[2];
        float cl = g_acc[3];
        float total = r + ct + no + cl;
        out[0] = total * inv_n;
        out[1] = r  * inv_n;
        out[2] = ct * inv_n;
        out[3] = no * inv_n;
        out[4] = cl * inv_n;
        g_acc[0] = 0.0f; g_acc[1] = 0.0f; g_acc[2] = 0.0f; g_acc[3] = 0.0f;
        g_block_count = 0u;
        __threadfence();
    }
}

extern "C" void kernel_launch(void* const* d_in, const int* in_sizes, int n_in,
                              void* d_out, int out_size) {
    const float* pred = (const float*)d_in[0];
    const float* tbox = (const float*)d_in[1];
    const float* tcls = (const float*)d_in[2];
    const unsigned int* objmap = (const unsigned int*)d_in[3];

    int ncells = in_sizes[1] / 4;             // target_boxes has 4 per cell
    int n_imgs = ncells / (S_GRID * S_GRID);  // 4096
    int ntiles = (ncells + WTILE - 1) / WTILE;   // 25088

    int dev = 0, sms = 148;
    cudaGetDevice(&dev);
    cudaDeviceGetAttribute(&sms, cudaDevAttrMultiProcessorCount, dev);
    int blocks = sms * 6;                     // 6 co-resident blocks/SM
    int max_blocks = (ntiles + WARPS - 1) / WARPS;
    if (blocks > max_blocks) blocks = max_blocks;
    int nwarps_total = blocks * WARPS;

    yolo_persistent_kernel<<<blocks, TPB>>>(pred, tbox, tcls, objmap,
                                            (float*)d_out, ncells, ntiles,
                                            nwarps_total, 1.0f / (float)n_imgs);
}